// round 1
// baseline (speedup 1.0000x reference)
#include <cuda_runtime.h>
#include <cuda_bf16.h>

// Piecewise-linear log-sigmoid approximation.
//   vals: [N] f32, x: [65] f32 (uniform linspace -10..10), y: [65] f32
//   out[i] = vals[i]                      if vals[i] <  x[0]
//          = 0                            if vals[i] >= x[64]
//          = y[k] + (v - x[k]) * slope[k] otherwise, k = searchsorted(x, v, right)-1
//
// Memory-bound streaming kernel: float4 I/O, tables+slopes in shared memory,
// arithmetic bucket index (uniform breakpoints) with a +/-1 fixup against the
// actual table to match searchsorted semantics bit-for-bit at rounding edges.

#define NSEG 64
#define NBRK 65

__device__ __forceinline__ float interp_one(
    float v,
    const float* __restrict__ sx,
    const float* __restrict__ sy,
    const float* __restrict__ ss,
    float x0, float xK, float inv_h)
{
    if (v < x0)  return v;       // identity below table
    if (v >= xK) return 0.0f;    // zero above table

    int idx = (int)floorf((v - x0) * inv_h);
    idx = max(0, min(idx, NSEG - 1));

    // Fixup against the actual fp32 table values so we exactly reproduce
    // searchsorted(x, v, side="right") - 1 on the stored breakpoints.
    float xl = sx[idx];
    if (v < xl) {
        idx -= 1;
        xl = sx[idx];
    } else {
        float xh = sx[idx + 1];
        if (v >= xh) {
            idx += 1;
            xl = xh;
        }
    }
    return fmaf(v - xl, ss[idx], sy[idx]);
}

__global__ __launch_bounds__(256)
void logsig_pwl_kernel(const float* __restrict__ vals,
                       const float* __restrict__ x,
                       const float* __restrict__ y,
                       float* __restrict__ out,
                       int n)
{
    __shared__ float sx[NBRK];
    __shared__ float sy[NBRK];
    __shared__ float ss[NSEG];

    int t = threadIdx.x;
    if (t < NBRK) {
        sx[t] = x[t];
        sy[t] = y[t];
    }
    __syncthreads();
    if (t < NSEG) {
        ss[t] = (sy[t + 1] - sy[t]) / (sx[t + 1] - sx[t]);
    }
    __syncthreads();

    const float x0   = sx[0];
    const float xK   = sx[NBRK - 1];
    const float inv_h = (float)NSEG / (xK - x0);

    // Vectorized main body: n4 float4s.
    int n4 = n >> 2;
    const float4* __restrict__ v4 = (const float4*)vals;
    float4* __restrict__ o4 = (float4*)out;

    int stride = gridDim.x * blockDim.x;
    for (int i = blockIdx.x * blockDim.x + t; i < n4; i += stride) {
        float4 v = v4[i];
        float4 o;
        o.x = interp_one(v.x, sx, sy, ss, x0, xK, inv_h);
        o.y = interp_one(v.y, sx, sy, ss, x0, xK, inv_h);
        o.z = interp_one(v.z, sx, sy, ss, x0, xK, inv_h);
        o.w = interp_one(v.w, sx, sy, ss, x0, xK, inv_h);
        o4[i] = o;
    }

    // Scalar tail (n not divisible by 4 — not the case here, but safe).
    for (int i = (n4 << 2) + blockIdx.x * blockDim.x + t; i < n; i += stride) {
        out[i] = interp_one(vals[i], sx, sy, ss, x0, xK, inv_h);
    }
}

extern "C" void kernel_launch(void* const* d_in, const int* in_sizes, int n_in,
                              void* d_out, int out_size)
{
    const float* vals = (const float*)d_in[0];
    const float* x    = (const float*)d_in[1];
    const float* y    = (const float*)d_in[2];
    float* out        = (float*)d_out;
    int n = in_sizes[0];

    // 148 SMs * 4 blocks/SM worth of 256-thread blocks, grid-stride.
    int blocks = 592;
    logsig_pwl_kernel<<<blocks, 256>>>(vals, x, y, out, n);
}

// round 2
// speedup vs baseline: 1.3774x; 1.3774x over previous
#include <cuda_runtime.h>
#include <cuda_bf16.h>

// Piecewise-linear log-sigmoid approximation (uniform breakpoints).
//   out = v                          if v <  x[0]
//       = 0                          if v >= x[64]
//       = y[k] + (v - x[k])*slope[k] otherwise
//
// Uniform linspace breakpoints -> arithmetic segment index + arithmetic x_lo
// (step 0.3125 is exact in fp32), so the only table access is ONE LDS.64 per
// element into a shared float2 {y_lo, slope} LUT. Full-occupancy grid-stride
// streaming with 2x float4 per iteration for MLP.

#define NSEG 64
#define NBRK 65

struct Tab { float y; float s; };

__device__ __forceinline__ float interp_one(
    float v, const float2* __restrict__ tab,
    float x0, float xK, float h, float inv_h)
{
    // segment index (uniform grid) with +/-1 fixup at rounding edges
    int idx = __float2int_rd((v - x0) * inv_h);
    idx = max(0, min(idx, NSEG - 1));
    float xl = fmaf((float)idx, h, x0);
    if (v < xl) {
        idx -= 1; xl -= h;
    } else {
        float xh = xl + h;
        if (v >= xh) { idx += 1; xl = xh; }
    }
    idx = max(0, min(idx, NSEG - 1));

    float2 ts = tab[idx];                     // single LDS.64
    float r = fmaf(v - xl, ts.y, ts.x);       // y_lo + (v-xl)*slope

    r = (v < x0) ? v : r;                     // identity below table
    r = (v >= xK) ? 0.0f : r;                 // zero above table
    return r;
}

__global__ __launch_bounds__(256)
void logsig_pwl_kernel(const float* __restrict__ vals,
                       const float* __restrict__ x,
                       const float* __restrict__ y,
                       float* __restrict__ out,
                       int n)
{
    __shared__ float2 tab[NSEG];
    __shared__ float sx0, sxK;

    int t = threadIdx.x;
    if (t < NSEG) {
        float xl = x[t], xh = x[t + 1];
        float yl = y[t], yh = y[t + 1];
        tab[t] = make_float2(yl, (yh - yl) / (xh - xl));
        if (t == 0) { sx0 = x[0]; sxK = x[NBRK - 1]; }
    }
    __syncthreads();

    const float x0 = sx0;
    const float xK = sxK;
    const float h     = (xK - x0) * (1.0f / NSEG);
    const float inv_h = (float)NSEG / (xK - x0);

    int n4 = n >> 2;
    const float4* __restrict__ v4 = (const float4*)vals;
    float4* __restrict__ o4 = (float4*)out;

    int tid    = blockIdx.x * blockDim.x + t;
    int stride = gridDim.x * blockDim.x;

    // main loop: 2 float4s per iteration, loads batched for MLP
    int i = tid;
    for (; i + stride < n4; i += 2 * stride) {
        float4 a = v4[i];
        float4 b = v4[i + stride];
        float4 oa, ob;
        oa.x = interp_one(a.x, tab, x0, xK, h, inv_h);
        oa.y = interp_one(a.y, tab, x0, xK, h, inv_h);
        oa.z = interp_one(a.z, tab, x0, xK, h, inv_h);
        oa.w = interp_one(a.w, tab, x0, xK, h, inv_h);
        ob.x = interp_one(b.x, tab, x0, xK, h, inv_h);
        ob.y = interp_one(b.y, tab, x0, xK, h, inv_h);
        ob.z = interp_one(b.z, tab, x0, xK, h, inv_h);
        ob.w = interp_one(b.w, tab, x0, xK, h, inv_h);
        o4[i]          = oa;
        o4[i + stride] = ob;
    }
    for (; i < n4; i += stride) {
        float4 a = v4[i];
        float4 oa;
        oa.x = interp_one(a.x, tab, x0, xK, h, inv_h);
        oa.y = interp_one(a.y, tab, x0, xK, h, inv_h);
        oa.z = interp_one(a.z, tab, x0, xK, h, inv_h);
        oa.w = interp_one(a.w, tab, x0, xK, h, inv_h);
        o4[i] = oa;
    }

    // scalar tail (n % 4 != 0 — not hit for this shape, kept for safety)
    for (int j = (n4 << 2) + tid; j < n; j += stride) {
        out[j] = interp_one(vals[j], tab, x0, xK, h, inv_h);
    }
}

extern "C" void kernel_launch(void* const* d_in, const int* in_sizes, int n_in,
                              void* d_out, int out_size)
{
    const float* vals = (const float*)d_in[0];
    const float* x    = (const float*)d_in[1];
    const float* y    = (const float*)d_in[2];
    float* out        = (float*)d_out;
    int n = in_sizes[0];

    // 148 SMs * 8 blocks/SM of 256 threads -> 64 warps/SM (full occupancy)
    int blocks = 1184;
    logsig_pwl_kernel<<<blocks, 256>>>(vals, x, y, out, n);
}

// round 3
// speedup vs baseline: 1.3843x; 1.0050x over previous
#include <cuda_runtime.h>
#include <cuda_bf16.h>

// Piecewise-linear log-sigmoid approximation (uniform breakpoints), v3.
//
// All three cases (identity below x0, PWL interior, zero above xK) are encoded
// in one extended LUT of {y, dy} pairs indexed by clamp(floor(u), -1, 64)+1
// where u = (v - x0)/h:
//   entry 0   (idx=-1): {x0-h, h}  -> y + (u-(-1))*h == v  (exact identity,
//                                      frac is NOT clamped so it extends)
//   entry k+1 (idx=k) : {y[k], y[k+1]-y[k]}  -> standard interp in index space
//   entry 65  (idx=64): {0, 0}     -> 0 for all v >= xK
// No branches, no predicates, one LDS.64 per element.
// Table replicated 4x across banks to cut divergent-index LDS conflicts.

#define NSEG  64
#define NBRK  65
#define NTAB  66          // -1 .. 64
#define NREP  4

__global__ __launch_bounds__(256)
void logsig_pwl_kernel(const float* __restrict__ vals,
                       const float* __restrict__ x,
                       const float* __restrict__ y,
                       float* __restrict__ out,
                       int n)
{
    __shared__ float2 tab[NTAB * NREP];   // replica r of entry e at [e*4 + r]
    __shared__ float  sc[2];              // x0, xK

    const int t = threadIdx.x;

    // Build extended table (66 entries x 4 replicas = 264 float2)
    for (int j = t; j < NTAB * NREP; j += blockDim.x) {
        int e = j >> 2;                   // 0..65
        float2 ts;
        float x0 = x[0], xK = x[NBRK - 1];
        float h  = (xK - x0) * (1.0f / NSEG);
        if (e == 0) {                     // idx = -1 : identity extension
            ts.x = x0 - h;
            ts.y = h;
        } else if (e == NTAB - 1) {       // idx = 64 : zero extension
            ts.x = 0.0f;
            ts.y = 0.0f;
        } else {                          // idx = e-1 : interior segment
            float yl = y[e - 1], yh = y[e];
            ts.x = yl;
            ts.y = yh - yl;               // slope in index space (= slope*h)
        }
        tab[j] = ts;
    }
    if (t == 0) { sc[0] = x[0]; sc[1] = x[NBRK - 1]; }
    __syncthreads();

    const float x0    = sc[0];
    const float xK    = sc[1];
    const float inv_h = (float)NSEG / (xK - x0);
    const float off   = -x0 * inv_h;      // u = v*inv_h + off

    // per-thread replicated table base (folds (t&3) into the pointer)
    const float2* __restrict__ mytab = tab + (t & (NREP - 1));

    const int n4 = n >> 2;
    const float4* __restrict__ v4 = (const float4*)vals;
    float4* __restrict__ o4 = (float4*)out;

    const int tid    = blockIdx.x * blockDim.x + t;
    const int stride = gridDim.x * blockDim.x;

    #define INTERP(V, O) do {                                          \
        float u  = fmaf((V), inv_h, off);                              \
        float uf = floorf(u);                                          \
        uf = fmaxf(-1.0f, fminf(uf, 64.0f));                           \
        float fr = u - uf;            /* unclamped -> extends guards */\
        int   e  = (int)uf + 1;       /* 0..65 */                      \
        float2 ts = mytab[e << 2];                                     \
        (O) = fmaf(fr, ts.y, ts.x);                                    \
    } while (0)

    int i = tid;
    for (; i + stride < n4; i += 2 * stride) {
        float4 a = v4[i];
        float4 b = v4[i + stride];
        float4 oa, ob;
        INTERP(a.x, oa.x); INTERP(a.y, oa.y);
        INTERP(a.z, oa.z); INTERP(a.w, oa.w);
        INTERP(b.x, ob.x); INTERP(b.y, ob.y);
        INTERP(b.z, ob.z); INTERP(b.w, ob.w);
        o4[i]          = oa;
        o4[i + stride] = ob;
    }
    for (; i < n4; i += stride) {
        float4 a = v4[i];
        float4 oa;
        INTERP(a.x, oa.x); INTERP(a.y, oa.y);
        INTERP(a.z, oa.z); INTERP(a.w, oa.w);
        o4[i] = oa;
    }

    // scalar tail (n % 4 != 0 — not hit for this shape, kept for safety)
    for (int j = (n4 << 2) + tid; j < n; j += stride) {
        float v = vals[j], o;
        INTERP(v, o);
        out[j] = o;
    }
    #undef INTERP
}

extern "C" void kernel_launch(void* const* d_in, const int* in_sizes, int n_in,
                              void* d_out, int out_size)
{
    const float* vals = (const float*)d_in[0];
    const float* x    = (const float*)d_in[1];
    const float* y    = (const float*)d_in[2];
    float* out        = (float*)d_out;
    int n = in_sizes[0];

    // 148 SMs * 8 CTAs of 256 threads -> 64 warps/SM, single wave
    int blocks = 1184;
    logsig_pwl_kernel<<<blocks, 256>>>(vals, x, y, out, n);
}

// round 4
// speedup vs baseline: 1.5272x; 1.1033x over previous
#include <cuda_runtime.h>
#include <cuda_bf16.h>

// Piecewise-linear log-sigmoid approximation (uniform breakpoints), v4.
//
// Index-space formulation (no branches): u = (v-x0)/h,
//   e = clamp(floor(u), -1, 64) + 1   (0..65)
//   out = Y[e] + (u - floor_clamped) * D[e]
// with guard entries: e=0 -> {x0-h, h} (exact identity for all v < x0),
// e=65 -> {0,0} (zero for all v >= xK).
//
// LUT is replicated 32x -- one private column per lane:
//   sy[e*32 + lane], sd[e*32 + lane] -> bank = lane  (ZERO conflicts by
//   construction, 1 phase per LDS.32, data-independent).
// Streaming loads/stores (__ldcs/__stcs): pure pass-through, no reuse.

#define NSEG  64
#define NBRK  65
#define NTAB  66          // entries for idx = -1 .. 64

__global__ __launch_bounds__(256)
void logsig_pwl_kernel(const float* __restrict__ vals,
                       const float* __restrict__ x,
                       const float* __restrict__ y,
                       float* __restrict__ out,
                       int n)
{
    __shared__ float sy[NTAB * 32];   // [entry][lane]
    __shared__ float sd[NTAB * 32];
    __shared__ float sc[2];           // x0, xK

    const int t = threadIdx.x;

    {
        const float x0 = x[0];
        const float xK = x[NBRK - 1];
        const float h  = (xK - x0) * (1.0f / NSEG);
        for (int j = t; j < NTAB * 32; j += blockDim.x) {
            int e = j >> 5;               // 0..65
            float yv, dv;
            if (e == 0)            { yv = x0 - h; dv = h;    }  // identity ext
            else if (e == NTAB-1)  { yv = 0.0f;   dv = 0.0f; }  // zero ext
            else                   { yv = y[e-1]; dv = y[e] - y[e-1]; }
            sy[j] = yv;
            sd[j] = dv;
        }
        if (t == 0) { sc[0] = x0; sc[1] = xK; }
    }
    __syncthreads();

    const float x0    = sc[0];
    const float xK    = sc[1];
    const float inv_h = (float)NSEG / (xK - x0);
    const float off   = -x0 * inv_h;          // u = v*inv_h + off

    // per-lane private table columns (bank == lane, conflict-free)
    const int lane = t & 31;
    const float* __restrict__ myy = sy + lane;
    const float* __restrict__ myd = sd + lane;

    const int n4 = n >> 2;
    const float4* __restrict__ v4 = (const float4*)vals;
    float4* __restrict__ o4 = (float4*)out;

    const int tid    = blockIdx.x * blockDim.x + t;
    const int stride = gridDim.x * blockDim.x;

    #define INTERP(V, O) do {                                           \
        float u  = fmaf((V), inv_h, off);                               \
        float uf = floorf(u);                                           \
        uf = fmaxf(-1.0f, fminf(uf, 64.0f));                            \
        float fr = u - uf;             /* unclamped: extends guards */  \
        int   e  = ((int)uf + 1) << 5; /* entry * 32 */                 \
        (O) = fmaf(fr, myd[e], myy[e]);                                 \
    } while (0)

    int i = tid;
    for (; i + stride < n4; i += 2 * stride) {
        float4 a = __ldcs(&v4[i]);
        float4 b = __ldcs(&v4[i + stride]);
        float4 oa, ob;
        INTERP(a.x, oa.x); INTERP(a.y, oa.y);
        INTERP(a.z, oa.z); INTERP(a.w, oa.w);
        INTERP(b.x, ob.x); INTERP(b.y, ob.y);
        INTERP(b.z, ob.z); INTERP(b.w, ob.w);
        __stcs(&o4[i], oa);
        __stcs(&o4[i + stride], ob);
    }
    for (; i < n4; i += stride) {
        float4 a = __ldcs(&v4[i]);
        float4 oa;
        INTERP(a.x, oa.x); INTERP(a.y, oa.y);
        INTERP(a.z, oa.z); INTERP(a.w, oa.w);
        __stcs(&o4[i], oa);
    }

    // scalar tail (n % 4 != 0 -- not hit for this shape, kept for safety)
    for (int j = (n4 << 2) + tid; j < n; j += stride) {
        float v = vals[j], o;
        INTERP(v, o);
        out[j] = o;
    }
    #undef INTERP
}

extern "C" void kernel_launch(void* const* d_in, const int* in_sizes, int n_in,
                              void* d_out, int out_size)
{
    const float* vals = (const float*)d_in[0];
    const float* x    = (const float*)d_in[1];
    const float* y    = (const float*)d_in[2];
    float* out        = (float*)d_out;
    int n = in_sizes[0];

    // 148 SMs * 8 CTAs of 256 threads -> 64 warps/SM, single wave
    int blocks = 1184;
    logsig_pwl_kernel<<<blocks, 256>>>(vals, x, y, out, n);
}

// round 6
// speedup vs baseline: 1.5396x; 1.0081x over previous
#include <cuda_runtime.h>
#include <cuda_bf16.h>

// Piecewise-linear log-sigmoid approximation (uniform breakpoints), v5.
//
// Index-space formulation (no branches): u = (v-x0)/h,
//   e = clamp(floor(u), -1, 64) + 1   (0..65)
//   out = Y[e] + (u - uf) * D[e]
// Guard entries: e=0 -> {x0-h, h} (exact identity for v < x0),
// e=65 -> {0,0} (zero for v >= xK).
//
// LUT: float2 {y, dy}, replicated 32x (one column per lane):
//   tab[e*32 + lane] -> LDS.64, conflict-free in its two half-warp phases.
// 4x-unrolled grid-stride loop, loads batched up front for MLP=4.

#define NSEG  64
#define NBRK  65
#define NTAB  66          // entries for idx = -1 .. 64

__global__ __launch_bounds__(256)
void logsig_pwl_kernel(const float* __restrict__ vals,
                       const float* __restrict__ x,
                       const float* __restrict__ y,
                       float* __restrict__ out,
                       int n)
{
    __shared__ float2 tab[NTAB * 32];   // [entry][lane] {y, dy}
    __shared__ float  sc[2];            // x0, xK

    const int t = threadIdx.x;

    {
        const float x0 = x[0];
        const float xK = x[NBRK - 1];
        const float h  = (xK - x0) * (1.0f / NSEG);
        for (int j = t; j < NTAB * 32; j += blockDim.x) {
            int e = j >> 5;               // 0..65
            float2 ts;
            if (e == 0)            { ts.x = x0 - h; ts.y = h;    }
            else if (e == NTAB-1)  { ts.x = 0.0f;   ts.y = 0.0f; }
            else                   { ts.x = y[e-1]; ts.y = y[e] - y[e-1]; }
            tab[j] = ts;
        }
        if (t == 0) { sc[0] = x0; sc[1] = xK; }
    }
    __syncthreads();

    const float x0    = sc[0];
    const float xK    = sc[1];
    const float inv_h = (float)NSEG / (xK - x0);
    const float off   = -x0 * inv_h;          // u = v*inv_h + off

    const int lane = t & 31;
    const float2* __restrict__ mytab = tab + lane;

    const int n4 = n >> 2;
    const float4* __restrict__ v4 = (const float4*)vals;
    float4* __restrict__ o4 = (float4*)out;

    const int tid    = blockIdx.x * blockDim.x + t;
    const int stride = gridDim.x * blockDim.x;

    #define INTERP(V, O) do {                                           \
        float u  = fmaf((V), inv_h, off);                               \
        float uf = floorf(u);                                           \
        uf = fmaxf(-1.0f, fminf(uf, 64.0f));                            \
        float fr = u - uf;             /* unclamped: extends guards */  \
        int   e  = ((int)uf + 1) << 5; /* entry * 32 */                 \
        float2 ts = mytab[e];                                           \
        (O) = fmaf(fr, ts.y, ts.x);                                     \
    } while (0)

    #define DO4(A, OA)                                                  \
        INTERP((A).x, (OA).x); INTERP((A).y, (OA).y);                   \
        INTERP((A).z, (OA).z); INTERP((A).w, (OA).w);

    int i = tid;
    // 4x unrolled main loop: all 4 LDG.128 issued before any LDS/compute
    for (; i + 3 * stride < n4; i += 4 * stride) {
        float4 a = __ldcs(&v4[i]);
        float4 b = __ldcs(&v4[i +     stride]);
        float4 c = __ldcs(&v4[i + 2 * stride]);
        float4 d = __ldcs(&v4[i + 3 * stride]);
        float4 oa, ob, oc, od;
        DO4(a, oa); DO4(b, ob); DO4(c, oc); DO4(d, od);
        __stcs(&o4[i],              oa);
        __stcs(&o4[i +     stride], ob);
        __stcs(&o4[i + 2 * stride], oc);
        __stcs(&o4[i + 3 * stride], od);
    }
    for (; i < n4; i += stride) {
        float4 a = __ldcs(&v4[i]);
        float4 oa;
        DO4(a, oa);
        __stcs(&o4[i], oa);
    }

    // scalar tail (n % 4 != 0 -- not hit for this shape, kept for safety)
    for (int j = (n4 << 2) + tid; j < n; j += stride) {
        float v = vals[j], o;
        INTERP(v, o);
        out[j] = o;
    }
    #undef DO4
    #undef INTERP
}

extern "C" void kernel_launch(void* const* d_in, const int* in_sizes, int n_in,
                              void* d_out, int out_size)
{
    const float* vals = (const float*)d_in[0];
    const float* x    = (const float*)d_in[1];
    const float* y    = (const float*)d_in[2];
    float* out        = (float*)d_out;
    int n = in_sizes[0];

    int blocks = 1184;   // 148 SMs * 8 CTAs of 256 threads (reg-permitting)
    logsig_pwl_kernel<<<blocks, 256>>>(vals, x, y, out, n);
}